// round 1
// baseline (speedup 1.0000x reference)
#include <cuda_runtime.h>
#include <math.h>

// ---------------------------------------------------------------------------
// Fused INR (Fourier features + SIREN MLP) — fp32 baseline with f32x2 FMA.
//
// Network: coords[L,3] -> FF(256) -> sin-layer(256->512) -> 5x sin-layer(512)
//          -> linear(512->3).
// One CTA per 64-point tile; activations resident in SMEM; weights streamed
// from L2 through a padded SMEM staging buffer; per-thread 8m x 16n register
// tile accumulated with packed fma.rn.f32x2 (Blackwell FFMA2 path).
// ---------------------------------------------------------------------------

#define TILE_M   64
#define THREADS  256
#define AS       66            // act row stride (floats): 64 + 2 pad (bank skew)
#define KC       16            // k-chunk staged per sync
#define WS       516           // w_s row stride (floats): 512 + 4 pad
#define OMEGA0   30.0f
#define TWO_PI_F 6.283185307179586f

typedef unsigned long long ull;

__device__ __forceinline__ void fma2(ull& d, ull a, ull b) {
    asm("fma.rn.f32x2 %0, %1, %2, %0;" : "+l"(d) : "l"(a), "l"(b));
}
__device__ __forceinline__ ull pack2(float lo, float hi) {
    ull r;
    asm("mov.b64 %0, {%1, %2};" : "=l"(r) : "f"(lo), "f"(hi));
    return r;
}
__device__ __forceinline__ void unpack2(ull v, float& lo, float& hi) {
    asm("mov.b64 {%0, %1}, %2;" : "=f"(lo), "=f"(hi) : "l"(v));
}

// Stage W[512][IN] chunk (columns kb..kb+KC) into wsm[kk][n] (stride WS).
template <int IN>
__device__ __forceinline__ void load_w_chunk(const float* __restrict__ Wg,
                                             int kb, float* __restrict__ wsm,
                                             int tid) {
#pragma unroll
    for (int r = 0; r < (512 * KC / 4) / THREADS; ++r) {   // 8 reps
        int flat = (r << 8) + tid;       // 0..2047
        int n = flat >> 2;               // output neuron 0..511
        int q = flat & 3;                // which float4 along k
        const float4 g =
            *reinterpret_cast<const float4*>(&Wg[n * IN + kb + (q << 2)]);
        int base = (q << 2) * WS + n;
        wsm[base]          = g.x;
        wsm[base + WS]     = g.y;
        wsm[base + 2 * WS] = g.z;
        wsm[base + 3 * WS] = g.w;
    }
}

// One dense layer 512 outputs <- IN inputs, sine activation, in-place on act.
template <int IN>
__device__ __forceinline__ void sine_layer(float* __restrict__ act,
                                           float* __restrict__ wsm,
                                           const float* __restrict__ Wg,
                                           const float* __restrict__ bg,
                                           int tid, int mg, int ng) {
    ull acc[64];
#pragma unroll
    for (int i = 0; i < 64; ++i) acc[i] = 0ull;   // (0.f, 0.f)

    for (int kb = 0; kb < IN; kb += KC) {
        load_w_chunk<IN>(Wg, kb, wsm, tid);
        __syncthreads();
#pragma unroll 2
        for (int kk = 0; kk < KC; ++kk) {
            const float* ar = &act[(kb + kk) * AS + (mg << 3)];
            ull h0 = *reinterpret_cast<const ull*>(ar + 0);
            ull h1 = *reinterpret_cast<const ull*>(ar + 2);
            ull h2 = *reinterpret_cast<const ull*>(ar + 4);
            ull h3 = *reinterpret_cast<const ull*>(ar + 6);
            const float* wr = &wsm[kk * WS + ng];
#pragma unroll
            for (int j = 0; j < 16; ++j) {
                float w = wr[j << 5];
                ull wp = pack2(w, w);
                fma2(acc[j * 4 + 0], h0, wp);
                fma2(acc[j * 4 + 1], h1, wp);
                fma2(acc[j * 4 + 2], h2, wp);
                fma2(acc[j * 4 + 3], h3, wp);
            }
        }
        __syncthreads();
    }

    // Epilogue: sin(omega0 * (acc + b)) -> act[n][m]
#pragma unroll
    for (int j = 0; j < 16; ++j) {
        int n = ng + (j << 5);
        float bv = bg[n];
        float* orow = &act[n * AS + (mg << 3)];
#pragma unroll
        for (int p = 0; p < 4; ++p) {
            float lo, hi;
            unpack2(acc[j * 4 + p], lo, hi);
            float2 sv;
            sv.x = sinf(OMEGA0 * (lo + bv));
            sv.y = sinf(OMEGA0 * (hi + bv));
            *reinterpret_cast<float2*>(&orow[p << 1]) = sv;
        }
    }
}

__global__ void __launch_bounds__(THREADS, 1)
inr_fused_kernel(const float* __restrict__ coords,
                 const float* __restrict__ B_ff,
                 const float* __restrict__ W_first,
                 const float* __restrict__ b_first,
                 const float* __restrict__ W_hidden,
                 const float* __restrict__ b_hidden,
                 const float* __restrict__ W_out,
                 const float* __restrict__ b_out,
                 float* __restrict__ out, int L) {
    extern __shared__ float sm[];
    float* act = sm;                       // 512 * AS
    float* wsm = sm + 512 * AS;            // KC * WS (reused for W_out)
    float* cs  = wsm + KC * WS;            // 64 * 3 coords
    float* bff = cs + TILE_M * 3;          // 3 * 128

    const int tid = threadIdx.x;
    const int mg  = tid >> 5;              // warp id: m-group (8 points)
    const int ng  = tid & 31;              // lane: n-group (16 outputs, stride 32)
    const int tile = blockIdx.x;
    const int p0 = tile * TILE_M;

    // ---- Stage coords + B_ff ----
    if (tid < TILE_M * 3) {
        int g = p0 * 3 + tid;
        cs[tid] = (g < L * 3) ? coords[g] : 0.0f;
    }
    for (int i = tid; i < 3 * 128; i += THREADS) bff[i] = B_ff[i];
    __syncthreads();

    // ---- Fourier features: act[0..127]=sin, act[128..255]=cos ----
    for (int idx = tid; idx < 128 * TILE_M; idx += THREADS) {
        int j = idx >> 6;
        int m = idx & 63;
        float pr = TWO_PI_F * (cs[m * 3 + 0] * bff[j] +
                               cs[m * 3 + 1] * bff[128 + j] +
                               cs[m * 3 + 2] * bff[256 + j]);
        float s, c;
        sincosf(pr, &s, &c);
        act[j * AS + m]         = s;
        act[(128 + j) * AS + m] = c;
    }
    __syncthreads();

    // ---- First sine layer: 256 -> 512 ----
    sine_layer<256>(act, wsm, W_first, b_first, tid, mg, ng);

    // ---- Five hidden sine layers: 512 -> 512 ----
    for (int l = 0; l < 5; ++l) {
        sine_layer<512>(act, wsm, W_hidden + l * 512 * 512,
                        b_hidden + l * 512, tid, mg, ng);
    }

    // ---- Output linear: 512 -> 3 ----
    for (int f = tid; f < 3 * 512; f += THREADS) wsm[f] = W_out[f];
    __syncthreads();
    if (tid < TILE_M * 3) {
        int m = tid / 3;
        int o = tid - 3 * m;
        const float* wr = &wsm[o * 512];
        const float* ar = &act[m];
        float accv = 0.0f;
#pragma unroll 8
        for (int k = 0; k < 512; ++k) accv = fmaf(wr[k], ar[k * AS], accv);
        int p = p0 + m;
        if (p < L) out[p * 3 + o] = accv + b_out[o];
    }
}

#define SMEM_BYTES ((512 * AS + KC * WS + TILE_M * 3 + 3 * 128) * sizeof(float))

extern "C" void kernel_launch(void* const* d_in, const int* in_sizes, int n_in,
                              void* d_out, int out_size) {
    const float* coords   = (const float*)d_in[0];
    const float* B_ff     = (const float*)d_in[1];
    const float* W_first  = (const float*)d_in[2];
    const float* b_first  = (const float*)d_in[3];
    const float* W_hidden = (const float*)d_in[4];
    const float* b_hidden = (const float*)d_in[5];
    const float* W_out    = (const float*)d_in[6];
    const float* b_out    = (const float*)d_in[7];
    float* out = (float*)d_out;

    int L = in_sizes[0] / 3;
    int tiles = (L + TILE_M - 1) / TILE_M;

    cudaFuncSetAttribute(inr_fused_kernel,
                         cudaFuncAttributeMaxDynamicSharedMemorySize,
                         (int)SMEM_BYTES);

    inr_fused_kernel<<<tiles, THREADS, SMEM_BYTES>>>(
        coords, B_ff, W_first, b_first, W_hidden, b_hidden, W_out, b_out,
        out, L);
}

// round 2
// speedup vs baseline: 1.4116x; 1.4116x over previous
#include <cuda_runtime.h>
#include <math.h>

// ---------------------------------------------------------------------------
// Fused INR (Fourier features + SIREN MLP) — fp32, packed f32x2 FMA, v2.
//
// v2 changes vs v1 (22.5ms, fma pipe 47.5%, occ 12.5%):
//   * 512 threads/CTA -> 16 warps (4/SMSP) for latency hiding
//   * per-thread tile 8m x 8n -> acc = 32 ull (64 regs), ~110 regs total
//   * register-pipelined weight streaming (LDG next chunk during compute)
//   * __sinf for the 6 sine layers (small args), precise sincosf for FF
// ---------------------------------------------------------------------------

#define TILE_M   64
#define THREADS  512
#define AS       66            // act row stride (floats): 64 + 2 pad
#define KC       16            // k-chunk staged per double-barrier
#define WS       516           // wsm row stride (floats): 512 + 4 pad
#define OMEGA0   30.0f
#define TWO_PI_F 6.283185307179586f

typedef unsigned long long ull;

__device__ __forceinline__ void fma2(ull& d, ull a, ull b) {
    asm("fma.rn.f32x2 %0, %1, %2, %0;" : "+l"(d) : "l"(a), "l"(b));
}
__device__ __forceinline__ ull pack2(float lo, float hi) {
    ull r;
    asm("mov.b64 %0, {%1, %2};" : "=l"(r) : "f"(lo), "f"(hi));
    return r;
}
__device__ __forceinline__ void unpack2(ull v, float& lo, float& hi) {
    asm("mov.b64 {%0, %1}, %2;" : "=f"(lo), "=f"(hi) : "l"(v));
}

// Load one KC-column chunk of W[512][IN] into registers (4 float4 / thread).
template <int IN>
__device__ __forceinline__ void ldg_chunk(const float* __restrict__ Wg, int kb,
                                          float4* wreg, int tid) {
#pragma unroll
    for (int r = 0; r < 4; ++r) {
        int flat = r * THREADS + tid;   // 0..2047
        int n = flat >> 2;              // output neuron 0..511
        int q = flat & 3;               // float4 index along k
        wreg[r] = *reinterpret_cast<const float4*>(&Wg[n * IN + kb + (q << 2)]);
    }
}

// Scatter the register chunk into wsm[kk][n] (transposed, stride WS).
__device__ __forceinline__ void sts_chunk(const float4* wreg,
                                          float* __restrict__ wsm, int tid) {
#pragma unroll
    for (int r = 0; r < 4; ++r) {
        int flat = r * THREADS + tid;
        int n = flat >> 2;
        int q = flat & 3;
        int base = (q << 2) * WS + n;
        wsm[base]          = wreg[r].x;
        wsm[base + WS]     = wreg[r].y;
        wsm[base + 2 * WS] = wreg[r].z;
        wsm[base + 3 * WS] = wreg[r].w;
    }
}

// One dense layer: 512 outputs <- IN inputs, sine activation, in-place on act.
template <int IN>
__device__ __forceinline__ void sine_layer(float* __restrict__ act,
                                           float* __restrict__ wsm,
                                           const float* __restrict__ Wg,
                                           const float* __restrict__ bg,
                                           int tid, int mg, int ng, int nh) {
    ull acc[4][8];
#pragma unroll
    for (int a = 0; a < 4; ++a)
#pragma unroll
        for (int b = 0; b < 8; ++b) acc[a][b] = 0ull;

    float4 wreg[4];
    ldg_chunk<IN>(Wg, 0, wreg, tid);

    const int NCH = IN / KC;
    for (int c = 0; c < NCH; ++c) {
        __syncthreads();                       // wsm free to overwrite
        sts_chunk(wreg, wsm, tid);
        __syncthreads();                       // wsm chunk visible
        if (c + 1 < NCH) ldg_chunk<IN>(Wg, (c + 1) * KC, wreg, tid);

        const int kb = c * KC;
#pragma unroll
        for (int kk = 0; kk < KC; ++kk) {
            const float* ar = &act[(kb + kk) * AS + (mg << 3)];
            ull h0 = *reinterpret_cast<const ull*>(ar + 0);
            ull h1 = *reinterpret_cast<const ull*>(ar + 2);
            ull h2 = *reinterpret_cast<const ull*>(ar + 4);
            ull h3 = *reinterpret_cast<const ull*>(ar + 6);
            const float* wr = &wsm[kk * WS + ng + (nh << 8)];
#pragma unroll
            for (int j = 0; j < 8; ++j) {
                float w = wr[j << 5];
                ull wp = pack2(w, w);
                fma2(acc[0][j], h0, wp);
                fma2(acc[1][j], h1, wp);
                fma2(acc[2][j], h2, wp);
                fma2(acc[3][j], h3, wp);
            }
        }
    }
    __syncthreads();   // all act reads finished before in-place overwrite

    // Epilogue: act[n][m] = __sinf(omega0*(acc + b)). Args are O(few) here,
    // well inside the fast-path range-reduction accuracy envelope.
#pragma unroll
    for (int j = 0; j < 8; ++j) {
        int n = ng + (j << 5) + (nh << 8);
        float ob = OMEGA0 * __ldg(&bg[n]);
        float* orow = &act[n * AS + (mg << 3)];
#pragma unroll
        for (int mi = 0; mi < 4; ++mi) {
            float lo, hi;
            unpack2(acc[mi][j], lo, hi);
            float2 sv;
            sv.x = __sinf(fmaf(OMEGA0, lo, ob));
            sv.y = __sinf(fmaf(OMEGA0, hi, ob));
            *reinterpret_cast<float2*>(&orow[mi << 1]) = sv;
        }
    }
}

__global__ void __launch_bounds__(THREADS, 1)
inr_fused_kernel(const float* __restrict__ coords,
                 const float* __restrict__ B_ff,
                 const float* __restrict__ W_first,
                 const float* __restrict__ b_first,
                 const float* __restrict__ W_hidden,
                 const float* __restrict__ b_hidden,
                 const float* __restrict__ W_out,
                 const float* __restrict__ b_out,
                 float* __restrict__ out, int L) {
    extern __shared__ float sm[];
    float* act = sm;                       // 512 * AS
    float* wsm = sm + 512 * AS;            // KC * WS (reused for W_out)
    float* cs  = wsm + KC * WS;            // 64 * 3 coords
    float* bff = cs + TILE_M * 3;          // 3 * 128

    const int tid = threadIdx.x;
    const int mg  = tid >> 6;              // 0..7: m-group (8 points)
    const int ng  = tid & 31;              // lane
    const int nh  = (tid >> 5) & 1;        // n-half (0: n<256, 1: n>=256)
    const int p0  = blockIdx.x * TILE_M;

    // ---- Stage coords + B_ff ----
    if (tid < TILE_M * 3) {
        int g = p0 * 3 + tid;
        cs[tid] = (g < L * 3) ? coords[g] : 0.0f;
    }
    if (tid >= THREADS - 384) bff[tid - (THREADS - 384)] = B_ff[tid - (THREADS - 384)];
    __syncthreads();

    // ---- Fourier features: act[0..127]=sin, act[128..255]=cos.
    //      Precise sincosf: args reach ~±200 here. ----
    for (int idx = tid; idx < 128 * TILE_M; idx += THREADS) {
        int j = idx >> 6;
        int m = idx & 63;
        float pr = TWO_PI_F * (cs[m * 3 + 0] * bff[j] +
                               cs[m * 3 + 1] * bff[128 + j] +
                               cs[m * 3 + 2] * bff[256 + j]);
        float s, c;
        sincosf(pr, &s, &c);
        act[j * AS + m]         = s;
        act[(128 + j) * AS + m] = c;
    }
    // (no barrier needed: sine_layer starts with __syncthreads)

    // ---- First sine layer: 256 -> 512 ----
    sine_layer<256>(act, wsm, W_first, b_first, tid, mg, ng, nh);

    // ---- Five hidden sine layers: 512 -> 512 ----
    for (int l = 0; l < 5; ++l) {
        sine_layer<512>(act, wsm, W_hidden + l * 512 * 512,
                        b_hidden + l * 512, tid, mg, ng, nh);
    }

    // ---- Output linear: 512 -> 3 ----
    __syncthreads();   // epilogue writes of last layer complete
    for (int f = tid; f < 3 * 512; f += THREADS) wsm[f] = W_out[f];
    __syncthreads();
    if (tid < TILE_M * 3) {
        int m = tid / 3;
        int o = tid - 3 * m;
        const float* wr = &wsm[o * 512];
        const float* ar = &act[m];
        float accv = 0.0f;
#pragma unroll 8
        for (int k = 0; k < 512; ++k) accv = fmaf(wr[k], ar[k * AS], accv);
        int p = p0 + m;
        if (p < L) out[p * 3 + o] = accv + b_out[o];
    }
}

#define SMEM_BYTES ((512 * AS + KC * WS + TILE_M * 3 + 3 * 128) * sizeof(float))

extern "C" void kernel_launch(void* const* d_in, const int* in_sizes, int n_in,
                              void* d_out, int out_size) {
    const float* coords   = (const float*)d_in[0];
    const float* B_ff     = (const float*)d_in[1];
    const float* W_first  = (const float*)d_in[2];
    const float* b_first  = (const float*)d_in[3];
    const float* W_hidden = (const float*)d_in[4];
    const float* b_hidden = (const float*)d_in[5];
    const float* W_out    = (const float*)d_in[6];
    const float* b_out    = (const float*)d_in[7];
    float* out = (float*)d_out;

    int L = in_sizes[0] / 3;
    int tiles = (L + TILE_M - 1) / TILE_M;

    cudaFuncSetAttribute(inr_fused_kernel,
                         cudaFuncAttributeMaxDynamicSharedMemorySize,
                         (int)SMEM_BYTES);

    inr_fused_kernel<<<tiles, THREADS, SMEM_BYTES>>>(
        coords, B_ff, W_first, b_first, W_hidden, b_hidden, W_out, b_out,
        out, L);
}

// round 3
// speedup vs baseline: 1.4119x; 1.0002x over previous
#include <cuda_runtime.h>
#include <math.h>

// ---------------------------------------------------------------------------
// Fused INR (Fourier features + SIREN MLP) — fp32, packed f32x2 FMA, v2.
//
// v2 changes vs v1 (22.5ms, fma pipe 47.5%, occ 12.5%):
//   * 512 threads/CTA -> 16 warps (4/SMSP) for latency hiding
//   * per-thread tile 8m x 8n -> acc = 32 ull (64 regs), ~110 regs total
//   * register-pipelined weight streaming (LDG next chunk during compute)
//   * __sinf for the 6 sine layers (small args), precise sincosf for FF
// ---------------------------------------------------------------------------

#define TILE_M   64
#define THREADS  512
#define AS       66            // act row stride (floats): 64 + 2 pad
#define KC       16            // k-chunk staged per double-barrier
#define WS       516           // wsm row stride (floats): 512 + 4 pad
#define OMEGA0   30.0f
#define TWO_PI_F 6.283185307179586f

typedef unsigned long long ull;

__device__ __forceinline__ void fma2(ull& d, ull a, ull b) {
    asm("fma.rn.f32x2 %0, %1, %2, %0;" : "+l"(d) : "l"(a), "l"(b));
}
__device__ __forceinline__ ull pack2(float lo, float hi) {
    ull r;
    asm("mov.b64 %0, {%1, %2};" : "=l"(r) : "f"(lo), "f"(hi));
    return r;
}
__device__ __forceinline__ void unpack2(ull v, float& lo, float& hi) {
    asm("mov.b64 {%0, %1}, %2;" : "=f"(lo), "=f"(hi) : "l"(v));
}

// Load one KC-column chunk of W[512][IN] into registers (4 float4 / thread).
template <int IN>
__device__ __forceinline__ void ldg_chunk(const float* __restrict__ Wg, int kb,
                                          float4* wreg, int tid) {
#pragma unroll
    for (int r = 0; r < 4; ++r) {
        int flat = r * THREADS + tid;   // 0..2047
        int n = flat >> 2;              // output neuron 0..511
        int q = flat & 3;               // float4 index along k
        wreg[r] = *reinterpret_cast<const float4*>(&Wg[n * IN + kb + (q << 2)]);
    }
}

// Scatter the register chunk into wsm[kk][n] (transposed, stride WS).
__device__ __forceinline__ void sts_chunk(const float4* wreg,
                                          float* __restrict__ wsm, int tid) {
#pragma unroll
    for (int r = 0; r < 4; ++r) {
        int flat = r * THREADS + tid;
        int n = flat >> 2;
        int q = flat & 3;
        int base = (q << 2) * WS + n;
        wsm[base]          = wreg[r].x;
        wsm[base + WS]     = wreg[r].y;
        wsm[base + 2 * WS] = wreg[r].z;
        wsm[base + 3 * WS] = wreg[r].w;
    }
}

// One dense layer: 512 outputs <- IN inputs, sine activation, in-place on act.
template <int IN>
__device__ __forceinline__ void sine_layer(float* __restrict__ act,
                                           float* __restrict__ wsm,
                                           const float* __restrict__ Wg,
                                           const float* __restrict__ bg,
                                           int tid, int mg, int ng, int nh) {
    ull acc[4][8];
#pragma unroll
    for (int a = 0; a < 4; ++a)
#pragma unroll
        for (int b = 0; b < 8; ++b) acc[a][b] = 0ull;

    float4 wreg[4];
    ldg_chunk<IN>(Wg, 0, wreg, tid);

    const int NCH = IN / KC;
    for (int c = 0; c < NCH; ++c) {
        __syncthreads();                       // wsm free to overwrite
        sts_chunk(wreg, wsm, tid);
        __syncthreads();                       // wsm chunk visible
        if (c + 1 < NCH) ldg_chunk<IN>(Wg, (c + 1) * KC, wreg, tid);

        const int kb = c * KC;
#pragma unroll
        for (int kk = 0; kk < KC; ++kk) {
            const float* ar = &act[(kb + kk) * AS + (mg << 3)];
            ull h0 = *reinterpret_cast<const ull*>(ar + 0);
            ull h1 = *reinterpret_cast<const ull*>(ar + 2);
            ull h2 = *reinterpret_cast<const ull*>(ar + 4);
            ull h3 = *reinterpret_cast<const ull*>(ar + 6);
            const float* wr = &wsm[kk * WS + ng + (nh << 8)];
#pragma unroll
            for (int j = 0; j < 8; ++j) {
                float w = wr[j << 5];
                ull wp = pack2(w, w);
                fma2(acc[0][j], h0, wp);
                fma2(acc[1][j], h1, wp);
                fma2(acc[2][j], h2, wp);
                fma2(acc[3][j], h3, wp);
            }
        }
    }
    __syncthreads();   // all act reads finished before in-place overwrite

    // Epilogue: act[n][m] = __sinf(omega0*(acc + b)). Args are O(few) here,
    // well inside the fast-path range-reduction accuracy envelope.
#pragma unroll
    for (int j = 0; j < 8; ++j) {
        int n = ng + (j << 5) + (nh << 8);
        float ob = OMEGA0 * __ldg(&bg[n]);
        float* orow = &act[n * AS + (mg << 3)];
#pragma unroll
        for (int mi = 0; mi < 4; ++mi) {
            float lo, hi;
            unpack2(acc[mi][j], lo, hi);
            float2 sv;
            sv.x = __sinf(fmaf(OMEGA0, lo, ob));
            sv.y = __sinf(fmaf(OMEGA0, hi, ob));
            *reinterpret_cast<float2*>(&orow[mi << 1]) = sv;
        }
    }
}

__global__ void __launch_bounds__(THREADS, 1)
inr_fused_kernel(const float* __restrict__ coords,
                 const float* __restrict__ B_ff,
                 const float* __restrict__ W_first,
                 const float* __restrict__ b_first,
                 const float* __restrict__ W_hidden,
                 const float* __restrict__ b_hidden,
                 const float* __restrict__ W_out,
                 const float* __restrict__ b_out,
                 float* __restrict__ out, int L) {
    extern __shared__ float sm[];
    float* act = sm;                       // 512 * AS
    float* wsm = sm + 512 * AS;            // KC * WS (reused for W_out)
    float* cs  = wsm + KC * WS;            // 64 * 3 coords
    float* bff = cs + TILE_M * 3;          // 3 * 128

    const int tid = threadIdx.x;
    const int mg  = tid >> 6;              // 0..7: m-group (8 points)
    const int ng  = tid & 31;              // lane
    const int nh  = (tid >> 5) & 1;        // n-half (0: n<256, 1: n>=256)
    const int p0  = blockIdx.x * TILE_M;

    // ---- Stage coords + B_ff ----
    if (tid < TILE_M * 3) {
        int g = p0 * 3 + tid;
        cs[tid] = (g < L * 3) ? coords[g] : 0.0f;
    }
    if (tid >= THREADS - 384) bff[tid - (THREADS - 384)] = B_ff[tid - (THREADS - 384)];
    __syncthreads();

    // ---- Fourier features: act[0..127]=sin, act[128..255]=cos.
    //      Precise sincosf: args reach ~±200 here. ----
    for (int idx = tid; idx < 128 * TILE_M; idx += THREADS) {
        int j = idx >> 6;
        int m = idx & 63;
        float pr = TWO_PI_F * (cs[m * 3 + 0] * bff[j] +
                               cs[m * 3 + 1] * bff[128 + j] +
                               cs[m * 3 + 2] * bff[256 + j]);
        float s, c;
        sincosf(pr, &s, &c);
        act[j * AS + m]         = s;
        act[(128 + j) * AS + m] = c;
    }
    // (no barrier needed: sine_layer starts with __syncthreads)

    // ---- First sine layer: 256 -> 512 ----
    sine_layer<256>(act, wsm, W_first, b_first, tid, mg, ng, nh);

    // ---- Five hidden sine layers: 512 -> 512 ----
    for (int l = 0; l < 5; ++l) {
        sine_layer<512>(act, wsm, W_hidden + l * 512 * 512,
                        b_hidden + l * 512, tid, mg, ng, nh);
    }

    // ---- Output linear: 512 -> 3 ----
    __syncthreads();   // epilogue writes of last layer complete
    for (int f = tid; f < 3 * 512; f += THREADS) wsm[f] = W_out[f];
    __syncthreads();
    if (tid < TILE_M * 3) {
        int m = tid / 3;
        int o = tid - 3 * m;
        const float* wr = &wsm[o * 512];
        const float* ar = &act[m];
        float accv = 0.0f;
#pragma unroll 8
        for (int k = 0; k < 512; ++k) accv = fmaf(wr[k], ar[k * AS], accv);
        int p = p0 + m;
        if (p < L) out[p * 3 + o] = accv + b_out[o];
    }
}

#define SMEM_BYTES ((512 * AS + KC * WS + TILE_M * 3 + 3 * 128) * sizeof(float))

extern "C" void kernel_launch(void* const* d_in, const int* in_sizes, int n_in,
                              void* d_out, int out_size) {
    const float* coords   = (const float*)d_in[0];
    const float* B_ff     = (const float*)d_in[1];
    const float* W_first  = (const float*)d_in[2];
    const float* b_first  = (const float*)d_in[3];
    const float* W_hidden = (const float*)d_in[4];
    const float* b_hidden = (const float*)d_in[5];
    const float* W_out    = (const float*)d_in[6];
    const float* b_out    = (const float*)d_in[7];
    float* out = (float*)d_out;

    int L = in_sizes[0] / 3;
    int tiles = (L + TILE_M - 1) / TILE_M;

    cudaFuncSetAttribute(inr_fused_kernel,
                         cudaFuncAttributeMaxDynamicSharedMemorySize,
                         (int)SMEM_BYTES);

    inr_fused_kernel<<<tiles, THREADS, SMEM_BYTES>>>(
        coords, B_ff, W_first, b_first, W_hidden, b_hidden, W_out, b_out,
        out, L);
}

// round 6
// speedup vs baseline: 4.4691x; 3.1654x over previous
#include <cuda_runtime.h>
#include <cuda_bf16.h>
#include <math.h>
#include <stdint.h>

// ===========================================================================
// Fused INR via warp-level mma.sync (bf16 hi/lo 3-product split, fp32 accum).
// No 'a'-suffix PTX features (harness targets plain sm_103).
//   prep kernel : W fp32 -> per-lane A-fragment-ordered bf16 hi/lo in GMEM
//   main kernel : CTA = 64 pts, 16 warps x (32 neurons x 64 pts);
//                 act planes (bf16 hi/lo) in swizzled SMEM, B via ldmatrix;
//                 A via coalesced LDG.128; sin epilogue in-place.
// R5 fix: bff staging covered only 320/384 elements -> strided loop.
// ===========================================================================

#define OMEGA0    30.0f
#define TWO_PI_F  6.283185307179586f
#define THREADS   512

#define NTILES    (512 + 5 * 1024)      // 5632 (mt,ks) tiles total
#define PLANE_U32 (NTILES * 128)        // u32 per plane (tile=128 u32)

__device__ __align__(16) uint32_t g_wfrag[2 * PLANE_U32];   // hi plane, lo plane

// ---- SMEM layout (bytes) ----
#define SM_WOUT  0                       // 1536 floats
#define SM_CS    6144                    // 192 floats
#define SM_BFF   6912                    // 384 floats
#define SM_HI    9216                    // act hi plane: 512 rows x 128B
#define SM_LO    (SM_HI + 65536)
#define SMEM_BYTES (SM_LO + 65536)       // 140288

// ---------------- helpers ----------------
__device__ __forceinline__ uint32_t smem_u32(const void* p) {
    uint32_t a;
    asm("{ .reg .u64 t; cvta.to.shared.u64 t, %1; cvt.u32.u64 %0, t; }"
        : "=r"(a) : "l"(p));
    return a;
}
__device__ __forceinline__ void mma16816(float* d, const uint4& a,
                                         uint32_t b0, uint32_t b1) {
    asm volatile(
        "mma.sync.aligned.m16n8k16.row.col.f32.bf16.bf16.f32 "
        "{%0,%1,%2,%3}, {%4,%5,%6,%7}, {%8,%9}, {%0,%1,%2,%3};"
        : "+f"(d[0]), "+f"(d[1]), "+f"(d[2]), "+f"(d[3])
        : "r"(a.x), "r"(a.y), "r"(a.z), "r"(a.w), "r"(b0), "r"(b1));
}
__device__ __forceinline__ void ldmx4t(uint32_t& r0, uint32_t& r1,
                                       uint32_t& r2, uint32_t& r3,
                                       uint32_t addr) {
    asm volatile(
        "ldmatrix.sync.aligned.m8n8.x4.trans.shared.b16 {%0,%1,%2,%3}, [%4];"
        : "=r"(r0), "=r"(r1), "=r"(r2), "=r"(r3) : "r"(addr));
}
__device__ __forceinline__ uint16_t bfb(float v) {
    __nv_bfloat16 h = __float2bfloat16(v);
    return *reinterpret_cast<uint16_t*>(&h);
}
__device__ __forceinline__ float bff2f(uint16_t b) {
    __nv_bfloat16 h = *reinterpret_cast<__nv_bfloat16*>(&b);
    return __bfloat162float(h);
}

// store v to (row, col n) in both planes (hi + residual lo), swizzled
__device__ __forceinline__ void store1(unsigned char* sm, int row, int n, float v) {
    uint32_t off = (uint32_t)row * 128u + (((uint32_t)n * 2u) ^ (((uint32_t)row & 7u) << 4));
    float hv; uint16_t hb = bfb(v); hv = bff2f(hb);
    *(uint16_t*)(sm + SM_HI + off) = hb;
    *(uint16_t*)(sm + SM_LO + off) = bfb(v - hv);
}

// ---------------- weight prep: fp32 -> fragment-ordered bf16 hi/lo ----------
__global__ void prep_weights(const float* __restrict__ Wf,
                             const float* __restrict__ Wh) {
    int idx = blockIdx.x * blockDim.x + threadIdx.x;
    if (idx >= 2 * PLANE_U32) return;
    int p   = idx / PLANE_U32;
    int rem = idx - p * PLANE_U32;
    int tile = rem >> 7;
    int li   = rem & 127;
    int lane = li >> 2, q = li & 3;

    const float* src; int K, mt, ks;
    if (tile < 512) { mt = tile >> 4; ks = tile & 15; K = 256; src = Wf; }
    else {
        int th = tile - 512;
        int l = th >> 10, tt = th & 1023;
        mt = tt >> 5; ks = tt & 31; K = 512;
        src = Wh + (size_t)l * 512 * 512;
    }
    int r  = lane >> 2, c2 = (lane & 3) * 2;
    int row = mt * 16 + r + (q & 1) * 8;
    int k   = ks * 16 + c2 + (q >> 1) * 8;
    float w0 = src[(size_t)row * K + k];
    float w1 = src[(size_t)row * K + k + 1];
    uint16_t h0 = bfb(w0), h1 = bfb(w1);
    uint16_t o0, o1;
    if (p == 0) { o0 = h0; o1 = h1; }
    else        { o0 = bfb(w0 - bff2f(h0)); o1 = bfb(w1 - bff2f(h1)); }
    g_wfrag[idx] = ((uint32_t)o1 << 16) | (uint32_t)o0;
}

// ---------------- one sine layer (KS k-steps of 16) ----------------
template <int KS>
__device__ __forceinline__ void run_layer(
    unsigned char* sm, uint32_t shi, uint32_t slo,
    const uint32_t* __restrict__ whi,   // g_wfrag + base*128
    const uint32_t* __restrict__ wlo,   // + PLANE_U32
    const float* __restrict__ bias,
    int wid, int lane)
{
    float acc[2][8][4];
#pragma unroll
    for (int a = 0; a < 2; ++a)
#pragma unroll
        for (int b = 0; b < 8; ++b)
#pragma unroll
            for (int c = 0; c < 4; ++c) acc[a][b][c] = 0.0f;

    const int r  = lane >> 2;
    const int cq = lane & 3;
    // ldmatrix per-lane address components
    const int mid  = lane >> 3;          // matrix id 0..3
    const int rrow = lane & 7;
    const uint32_t rswz = (uint32_t)rrow << 4;
    const uint32_t krow_off = ((uint32_t)((mid & 1) * 8 + rrow)) * 128u;
    const uint32_t nb_base  = (uint32_t)((mid >> 1) * 8) * 2u;

#pragma unroll 1
    for (int ks = 0; ks < KS; ++ks) {
        // ---- A fragments (coalesced LDG.128 from fragment-ordered GMEM) ----
        const int t0 = (wid * 2 + 0) * KS + ks;
        const int t1 = (wid * 2 + 1) * KS + ks;
        const uint4 Ah0 = *(const uint4*)(whi + (size_t)t0 * 128 + lane * 4);
        const uint4 Al0 = *(const uint4*)(wlo + (size_t)t0 * 128 + lane * 4);
        const uint4 Ah1 = *(const uint4*)(whi + (size_t)t1 * 128 + lane * 4);
        const uint4 Al1 = *(const uint4*)(wlo + (size_t)t1 * 128 + lane * 4);

        // ---- B fragments via ldmatrix.x4.trans (4 per plane, n=16 each) ----
        uint32_t Bh[16], Bl[16];
        const uint32_t kbase = (uint32_t)ks * 16u * 128u + krow_off;
#pragma unroll
        for (int j = 0; j < 4; ++j) {
            uint32_t nb = ((uint32_t)j * 32u + nb_base) ^ rswz;
            ldmx4t(Bh[4 * j], Bh[4 * j + 1], Bh[4 * j + 2], Bh[4 * j + 3],
                   shi + kbase + nb);
        }
#pragma unroll
        for (int j = 0; j < 4; ++j) {
            uint32_t nb = ((uint32_t)j * 32u + nb_base) ^ rswz;
            ldmx4t(Bl[4 * j], Bl[4 * j + 1], Bl[4 * j + 2], Bl[4 * j + 3],
                   slo + kbase + nb);
        }

        // ---- MMAs: 2 m-tiles x 8 n-tiles x 3 products ----
#pragma unroll
        for (int nt = 0; nt < 8; ++nt) {
            const uint32_t bh0 = Bh[nt * 2], bh1 = Bh[nt * 2 + 1];
            const uint32_t bl0 = Bl[nt * 2], bl1 = Bl[nt * 2 + 1];
            mma16816(acc[0][nt], Ah0, bh0, bh1);
            mma16816(acc[0][nt], Ah0, bl0, bl1);
            mma16816(acc[0][nt], Al0, bh0, bh1);
            mma16816(acc[1][nt], Ah1, bh0, bh1);
            mma16816(acc[1][nt], Ah1, bl0, bl1);
            mma16816(acc[1][nt], Al1, bh0, bh1);
        }
    }
    __syncthreads();   // all reads of act done -> safe to overwrite in place

    // ---- epilogue: sin(omega0*(acc+b)) -> act planes ----
#pragma unroll
    for (int mtl = 0; mtl < 2; ++mtl) {
        const int row0 = wid * 32 + mtl * 16 + r;
        const int row1 = row0 + 8;
        const float ob0 = OMEGA0 * __ldg(bias + row0);
        const float ob1 = OMEGA0 * __ldg(bias + row1);
        const uint32_t sw0 = ((uint32_t)row0 & 7u) << 4;
        const uint32_t sw1 = ((uint32_t)row1 & 7u) << 4;
#pragma unroll
        for (int nt = 0; nt < 8; ++nt) {
            const int n = nt * 8 + cq * 2;
            float v00 = __sinf(fmaf(OMEGA0, acc[mtl][nt][0], ob0));
            float v01 = __sinf(fmaf(OMEGA0, acc[mtl][nt][1], ob0));
            float v10 = __sinf(fmaf(OMEGA0, acc[mtl][nt][2], ob1));
            float v11 = __sinf(fmaf(OMEGA0, acc[mtl][nt][3], ob1));
            uint16_t h00 = bfb(v00), h01 = bfb(v01);
            uint16_t h10 = bfb(v10), h11 = bfb(v11);
            uint32_t off0 = (uint32_t)row0 * 128u + (((uint32_t)n * 2u) ^ sw0);
            uint32_t off1 = (uint32_t)row1 * 128u + (((uint32_t)n * 2u) ^ sw1);
            *(uint32_t*)(sm + SM_HI + off0) = ((uint32_t)h01 << 16) | h00;
            *(uint32_t*)(sm + SM_HI + off1) = ((uint32_t)h11 << 16) | h10;
            uint32_t l00 = (uint32_t)bfb(v00 - bff2f(h00));
            uint32_t l01 = (uint32_t)bfb(v01 - bff2f(h01));
            uint32_t l10 = (uint32_t)bfb(v10 - bff2f(h10));
            uint32_t l11 = (uint32_t)bfb(v11 - bff2f(h11));
            *(uint32_t*)(sm + SM_LO + off0) = (l01 << 16) | l00;
            *(uint32_t*)(sm + SM_LO + off1) = (l11 << 16) | l10;
        }
    }
    __syncthreads();   // next layer may read
}

// ---------------- main kernel ----------------
__global__ void __launch_bounds__(THREADS, 1)
inr_mma_kernel(const float* __restrict__ coords,
               const float* __restrict__ B_ff,
               const float* __restrict__ b_first,
               const float* __restrict__ b_hidden,
               const float* __restrict__ W_out,
               const float* __restrict__ b_out,
               float* __restrict__ out, int L)
{
    extern __shared__ unsigned char sm[];
    float* wout = (float*)(sm + SM_WOUT);
    float* cs   = (float*)(sm + SM_CS);
    float* bff  = (float*)(sm + SM_BFF);
    const uint32_t shi = smem_u32(sm + SM_HI);
    const uint32_t slo = smem_u32(sm + SM_LO);

    const int tid  = threadIdx.x;
    const int wid  = tid >> 5;
    const int lane = tid & 31;
    const int p0   = blockIdx.x * 64;

    if (tid < 192) {
        int g = p0 * 3 + tid;
        cs[tid] = (g < L * 3) ? coords[g] : 0.0f;
    }
    for (int i = tid; i < 384; i += THREADS) bff[i] = B_ff[i];   // R5 FIX
    __syncthreads();

    // Fourier features (precise sincos; args up to ~±200)
    for (int e = tid; e < 8192; e += THREADS) {
        int j = e >> 6, m = e & 63;
        float pr = TWO_PI_F * (cs[m * 3 + 0] * bff[j] +
                               cs[m * 3 + 1] * bff[128 + j] +
                               cs[m * 3 + 2] * bff[256 + j]);
        float sv, cv;
        sincosf(pr, &sv, &cv);
        store1(sm, j, m, sv);
        store1(sm, 128 + j, m, cv);
    }
    __syncthreads();

    // layer 0: K=256 (16 k-steps)
    run_layer<16>(sm, shi, slo, g_wfrag, g_wfrag + PLANE_U32, b_first, wid, lane);
    // hidden layers: K=512 (32 k-steps)
#pragma unroll 1
    for (int l = 0; l < 5; ++l) {
        const size_t base = (size_t)(512 + l * 1024) * 128;
        run_layer<32>(sm, shi, slo, g_wfrag + base,
                      g_wfrag + PLANE_U32 + base,
                      b_hidden + l * 512, wid, lane);
    }

    // output linear 512 -> 3 (fp32, hi+lo reconstruct)
    for (int f = tid; f < 1536; f += THREADS) wout[f] = W_out[f];
    __syncthreads();
    if (tid < 192) {
        const int p = tid & 63, o = tid >> 6;
        float acc = 0.0f;
#pragma unroll 4
        for (int k = 0; k < 512; ++k) {
            uint32_t off = (uint32_t)k * 128u +
                           (((uint32_t)p * 2u) ^ (((uint32_t)k & 7u) << 4));
            float h = bff2f(*(uint16_t*)(sm + SM_HI + off)) +
                      bff2f(*(uint16_t*)(sm + SM_LO + off));
            acc = fmaf(h, wout[o * 512 + k], acc);
        }
        int gp = p0 + p;
        if (gp < L) out[gp * 3 + o] = acc + __ldg(b_out + o);
    }
}

// ---------------- launcher ----------------
extern "C" void kernel_launch(void* const* d_in, const int* in_sizes, int n_in,
                              void* d_out, int out_size) {
    const float* coords   = (const float*)d_in[0];
    const float* B_ff     = (const float*)d_in[1];
    const float* W_first  = (const float*)d_in[2];
    const float* b_first  = (const float*)d_in[3];
    const float* W_hidden = (const float*)d_in[4];
    const float* b_hidden = (const float*)d_in[5];
    const float* W_out    = (const float*)d_in[6];
    const float* b_out    = (const float*)d_in[7];
    float* out = (float*)d_out;

    int L = in_sizes[0] / 3;
    int tiles = (L + 63) / 64;

    const int prep_n = 2 * PLANE_U32;
    prep_weights<<<(prep_n + 255) / 256, 256>>>(W_first, W_hidden);

    cudaFuncSetAttribute(inr_mma_kernel,
                         cudaFuncAttributeMaxDynamicSharedMemorySize,
                         SMEM_BYTES);
    inr_mma_kernel<<<tiles, THREADS, SMEM_BYTES>>>(
        coords, B_ff, b_first, b_hidden, W_out, b_out, out, L);
}

// round 7
// speedup vs baseline: 4.5859x; 1.0261x over previous
#include <cuda_runtime.h>
#include <cuda_bf16.h>
#include <math.h>
#include <stdint.h>

// ===========================================================================
// Fused INR via warp-level mma.sync (bf16 hi/lo 3-product split, fp32 accum).
// R6: A-fragment prefetch (1 k-step ahead), B in two half-batches (reg budget),
//     sin epilogue computed before the read-barrier, fast exact FF reduction.
// ===========================================================================

#define OMEGA0    30.0f
#define TWO_PI_F  6.283185307179586f
#define THREADS   512

#define NTILES    (512 + 5 * 1024)      // 5632 (mt,ks) tiles total
#define PLANE_U32 (NTILES * 128)        // u32 per plane (tile=128 u32)

__device__ __align__(16) uint32_t g_wfrag[2 * PLANE_U32];   // hi plane, lo plane

// ---- SMEM layout (bytes) ----
#define SM_WOUT  0                       // 1536 floats
#define SM_CS    6144                    // 192 floats
#define SM_BFF   6912                    // 384 floats
#define SM_HI    9216                    // act hi plane: 512 rows x 128B
#define SM_LO    (SM_HI + 65536)
#define SMEM_BYTES (SM_LO + 65536)       // 140288

// ---------------- helpers ----------------
__device__ __forceinline__ uint32_t smem_u32(const void* p) {
    uint32_t a;
    asm("{ .reg .u64 t; cvta.to.shared.u64 t, %1; cvt.u32.u64 %0, t; }"
        : "=r"(a) : "l"(p));
    return a;
}
__device__ __forceinline__ void mma16816(float* d, const uint4& a,
                                         uint32_t b0, uint32_t b1) {
    asm volatile(
        "mma.sync.aligned.m16n8k16.row.col.f32.bf16.bf16.f32 "
        "{%0,%1,%2,%3}, {%4,%5,%6,%7}, {%8,%9}, {%0,%1,%2,%3};"
        : "+f"(d[0]), "+f"(d[1]), "+f"(d[2]), "+f"(d[3])
        : "r"(a.x), "r"(a.y), "r"(a.z), "r"(a.w), "r"(b0), "r"(b1));
}
__device__ __forceinline__ void ldmx4t(uint32_t& r0, uint32_t& r1,
                                       uint32_t& r2, uint32_t& r3,
                                       uint32_t addr) {
    asm volatile(
        "ldmatrix.sync.aligned.m8n8.x4.trans.shared.b16 {%0,%1,%2,%3}, [%4];"
        : "=r"(r0), "=r"(r1), "=r"(r2), "=r"(r3) : "r"(addr));
}
__device__ __forceinline__ uint16_t bfb(float v) {
    __nv_bfloat16 h = __float2bfloat16(v);
    return *reinterpret_cast<uint16_t*>(&h);
}
__device__ __forceinline__ float bff2f(uint16_t b) {
    __nv_bfloat16 h = *reinterpret_cast<__nv_bfloat16*>(&b);
    return __bfloat162float(h);
}

// store v to (row, col n) in both planes (hi + residual lo), swizzled
__device__ __forceinline__ void store1(unsigned char* sm, int row, int n, float v) {
    uint32_t off = (uint32_t)row * 128u + (((uint32_t)n * 2u) ^ (((uint32_t)row & 7u) << 4));
    float hv; uint16_t hb = bfb(v); hv = bff2f(hb);
    *(uint16_t*)(sm + SM_HI + off) = hb;
    *(uint16_t*)(sm + SM_LO + off) = bfb(v - hv);
}

// ---------------- weight prep: fp32 -> fragment-ordered bf16 hi/lo ----------
__global__ void prep_weights(const float* __restrict__ Wf,
                             const float* __restrict__ Wh) {
    int idx = blockIdx.x * blockDim.x + threadIdx.x;
    if (idx >= 2 * PLANE_U32) return;
    int p   = idx / PLANE_U32;
    int rem = idx - p * PLANE_U32;
    int tile = rem >> 7;
    int li   = rem & 127;
    int lane = li >> 2, q = li & 3;

    const float* src; int K, mt, ks;
    if (tile < 512) { mt = tile >> 4; ks = tile & 15; K = 256; src = Wf; }
    else {
        int th = tile - 512;
        int l = th >> 10, tt = th & 1023;
        mt = tt >> 5; ks = tt & 31; K = 512;
        src = Wh + (size_t)l * 512 * 512;
    }
    int r  = lane >> 2, c2 = (lane & 3) * 2;
    int row = mt * 16 + r + (q & 1) * 8;
    int k   = ks * 16 + c2 + (q >> 1) * 8;
    float w0 = src[(size_t)row * K + k];
    float w1 = src[(size_t)row * K + k + 1];
    uint16_t h0 = bfb(w0), h1 = bfb(w1);
    uint16_t o0, o1;
    if (p == 0) { o0 = h0; o1 = h1; }
    else        { o0 = bfb(w0 - bff2f(h0)); o1 = bfb(w1 - bff2f(h1)); }
    g_wfrag[idx] = ((uint32_t)o1 << 16) | (uint32_t)o0;
}

// ---------------- one sine layer (KS k-steps of 16) ----------------
template <int KS>
__device__ __forceinline__ void run_layer(
    unsigned char* sm, uint32_t shi, uint32_t slo,
    const uint32_t* __restrict__ whi,
    const uint32_t* __restrict__ wlo,
    const float* __restrict__ bias,
    int wid, int lane)
{
    float acc[2][8][4];
#pragma unroll
    for (int a = 0; a < 2; ++a)
#pragma unroll
        for (int b = 0; b < 8; ++b)
#pragma unroll
            for (int c = 0; c < 4; ++c) acc[a][b][c] = 0.0f;

    const int r  = lane >> 2;
    const int cq = lane & 3;
    const int mid  = lane >> 3;
    const int rrow = lane & 7;
    const uint32_t rswz = (uint32_t)rrow << 4;
    const uint32_t krow_off = ((uint32_t)((mid & 1) * 8 + rrow)) * 128u;
    const uint32_t nb_base  = (uint32_t)((mid >> 1) * 8) * 2u;

    const uint32_t* pA0h = whi + (size_t)((wid * 2 + 0) * KS) * 128 + lane * 4;
    const uint32_t* pA0l = wlo + (size_t)((wid * 2 + 0) * KS) * 128 + lane * 4;
    const uint32_t* pA1h = whi + (size_t)((wid * 2 + 1) * KS) * 128 + lane * 4;
    const uint32_t* pA1l = wlo + (size_t)((wid * 2 + 1) * KS) * 128 + lane * 4;

    // prefetch A for ks=0
    uint4 Ah0 = *(const uint4*)pA0h;
    uint4 Al0 = *(const uint4*)pA0l;
    uint4 Ah1 = *(const uint4*)pA1h;
    uint4 Al1 = *(const uint4*)pA1l;

#pragma unroll 1
    for (int ks = 0; ks < KS; ++ks) {
        // ---- prefetch next A (issued before any consumer of current A) ----
        uint4 nAh0, nAl0, nAh1, nAl1;
        if (ks + 1 < KS) {
            nAh0 = *(const uint4*)(pA0h + (ks + 1) * 128);
            nAl0 = *(const uint4*)(pA0l + (ks + 1) * 128);
            nAh1 = *(const uint4*)(pA1h + (ks + 1) * 128);
            nAl1 = *(const uint4*)(pA1l + (ks + 1) * 128);
        }

        const uint32_t kbase = (uint32_t)ks * 16u * 128u + krow_off;

        // ---- two half-batches of 4 n-tiles (reg budget for A prefetch) ----
#pragma unroll
        for (int h = 0; h < 2; ++h) {
            uint32_t Bh[8], Bl[8];
#pragma unroll
            for (int j = 0; j < 2; ++j) {
                uint32_t nb = ((uint32_t)(h * 2 + j) * 32u + nb_base) ^ rswz;
                ldmx4t(Bh[4 * j], Bh[4 * j + 1], Bh[4 * j + 2], Bh[4 * j + 3],
                       shi + kbase + nb);
                ldmx4t(Bl[4 * j], Bl[4 * j + 1], Bl[4 * j + 2], Bl[4 * j + 3],
                       slo + kbase + nb);
            }
#pragma unroll
            for (int ntl = 0; ntl < 4; ++ntl) {
                const int nt = h * 4 + ntl;
                const uint32_t bh0 = Bh[ntl * 2], bh1 = Bh[ntl * 2 + 1];
                const uint32_t bl0 = Bl[ntl * 2], bl1 = Bl[ntl * 2 + 1];
                mma16816(acc[0][nt], Ah0, bh0, bh1);
                mma16816(acc[0][nt], Ah0, bl0, bl1);
                mma16816(acc[0][nt], Al0, bh0, bh1);
                mma16816(acc[1][nt], Ah1, bh0, bh1);
                mma16816(acc[1][nt], Ah1, bl0, bl1);
                mma16816(acc[1][nt], Al1, bh0, bh1);
            }
        }
        Ah0 = nAh0; Al0 = nAl0; Ah1 = nAh1; Al1 = nAl1;
    }

    // ---- sin + hi/lo split into acc regs BEFORE the read-barrier ----
#pragma unroll
    for (int mtl = 0; mtl < 2; ++mtl) {
        const int row0 = wid * 32 + mtl * 16 + r;
        const float ob0 = OMEGA0 * __ldg(bias + row0);
        const float ob1 = OMEGA0 * __ldg(bias + row0 + 8);
#pragma unroll
        for (int nt = 0; nt < 8; ++nt) {
            float v00 = __sinf(fmaf(OMEGA0, acc[mtl][nt][0], ob0));
            float v01 = __sinf(fmaf(OMEGA0, acc[mtl][nt][1], ob0));
            float v10 = __sinf(fmaf(OMEGA0, acc[mtl][nt][2], ob1));
            float v11 = __sinf(fmaf(OMEGA0, acc[mtl][nt][3], ob1));
            uint16_t h00 = bfb(v00), h01 = bfb(v01);
            uint16_t h10 = bfb(v10), h11 = bfb(v11);
            uint32_t l00 = (uint32_t)bfb(v00 - bff2f(h00));
            uint32_t l01 = (uint32_t)bfb(v01 - bff2f(h01));
            uint32_t l10 = (uint32_t)bfb(v10 - bff2f(h10));
            uint32_t l11 = (uint32_t)bfb(v11 - bff2f(h11));
            acc[mtl][nt][0] = __uint_as_float(((uint32_t)h01 << 16) | h00);
            acc[mtl][nt][1] = __uint_as_float(((uint32_t)h11 << 16) | h10);
            acc[mtl][nt][2] = __uint_as_float((l01 << 16) | l00);
            acc[mtl][nt][3] = __uint_as_float((l11 << 16) | l10);
        }
    }
    __syncthreads();   // all reads of act done -> safe to overwrite in place

#pragma unroll
    for (int mtl = 0; mtl < 2; ++mtl) {
        const int row0 = wid * 32 + mtl * 16 + r;
        const int row1 = row0 + 8;
        const uint32_t sw0 = ((uint32_t)row0 & 7u) << 4;
        const uint32_t sw1 = ((uint32_t)row1 & 7u) << 4;
#pragma unroll
        for (int nt = 0; nt < 8; ++nt) {
            const int n = nt * 8 + cq * 2;
            uint32_t off0 = (uint32_t)row0 * 128u + (((uint32_t)n * 2u) ^ sw0);
            uint32_t off1 = (uint32_t)row1 * 128u + (((uint32_t)n * 2u) ^ sw1);
            *(uint32_t*)(sm + SM_HI + off0) = __float_as_uint(acc[mtl][nt][0]);
            *(uint32_t*)(sm + SM_HI + off1) = __float_as_uint(acc[mtl][nt][1]);
            *(uint32_t*)(sm + SM_LO + off0) = __float_as_uint(acc[mtl][nt][2]);
            *(uint32_t*)(sm + SM_LO + off1) = __float_as_uint(acc[mtl][nt][3]);
        }
    }
    __syncthreads();   // next layer may read
}

// ---------------- main kernel ----------------
__global__ void __launch_bounds__(THREADS, 1)
inr_mma_kernel(const float* __restrict__ coords,
               const float* __restrict__ B_ff,
               const float* __restrict__ b_first,
               const float* __restrict__ b_hidden,
               const float* __restrict__ W_out,
               const float* __restrict__ b_out,
               float* __restrict__ out, int L)
{
    extern __shared__ unsigned char sm[];
    float* wout = (float*)(sm + SM_WOUT);
    float* cs   = (float*)(sm + SM_CS);
    float* bff  = (float*)(sm + SM_BFF);
    const uint32_t shi = smem_u32(sm + SM_HI);
    const uint32_t slo = smem_u32(sm + SM_LO);

    const int tid  = threadIdx.x;
    const int wid  = tid >> 5;
    const int lane = tid & 31;
    const int p0   = blockIdx.x * 64;

    if (tid < 192) {
        int g = p0 * 3 + tid;
        cs[tid] = (g < L * 3) ? coords[g] : 0.0f;
    }
    for (int i = tid; i < 384; i += THREADS) bff[i] = B_ff[i];
    __syncthreads();

    // Fourier features. sin(2*pi*t) == sin(2*pi*(t - rint(t))): exact
    // reduction before the 2*pi scale keeps the fast __sinf path accurate.
    for (int e = tid; e < 8192; e += THREADS) {
        int j = e >> 6, m = e & 63;
        float t = cs[m * 3 + 0] * bff[j] +
                  cs[m * 3 + 1] * bff[128 + j] +
                  cs[m * 3 + 2] * bff[256 + j];
        float f = t - rintf(t);
        float ang = TWO_PI_F * f;
        store1(sm, j, m, __sinf(ang));
        store1(sm, 128 + j, m, __cosf(ang));
    }
    __syncthreads();

    // layer 0: K=256 (16 k-steps)
    run_layer<16>(sm, shi, slo, g_wfrag, g_wfrag + PLANE_U32, b_first, wid, lane);
    // hidden layers: K=512 (32 k-steps)
#pragma unroll 1
    for (int l = 0; l < 5; ++l) {
        const size_t base = (size_t)(512 + l * 1024) * 128;
        run_layer<32>(sm, shi, slo, g_wfrag + base,
                      g_wfrag + PLANE_U32 + base,
                      b_hidden + l * 512, wid, lane);
    }

    // output linear 512 -> 3 (fp32, hi+lo reconstruct)
    for (int f = tid; f < 1536; f += THREADS) wout[f] = W_out[f];
    __syncthreads();
    if (tid < 192) {
        const int p = tid & 63, o = tid >> 6;
        float acc = 0.0f;
#pragma unroll 4
        for (int k = 0; k < 512; ++k) {
            uint32_t off = (uint32_t)k * 128u +
                           (((uint32_t)p * 2u) ^ (((uint32_t)k & 7u) << 4));
            float h = bff2f(*(uint16_t*)(sm + SM_HI + off)) +
                      bff2f(*(uint16_t*)(sm + SM_LO + off));
            acc = fmaf(h, wout[o * 512 + k], acc);
        }
        int gp = p0 + p;
        if (gp < L) out[gp * 3 + o] = acc + __ldg(b_out + o);
    }
}

// ---------------- launcher ----------------
extern "C" void kernel_launch(void* const* d_in, const int* in_sizes, int n_in,
                              void* d_out, int out_size) {
    const float* coords   = (const float*)d_in[0];
    const float* B_ff     = (const float*)d_in[1];
    const float* W_first  = (const float*)d_in[2];
    const float* b_first  = (const float*)d_in[3];
    const float* W_hidden = (const float*)d_in[4];
    const float* b_hidden = (const float*)d_in[5];
    const float* W_out    = (const float*)d_in[6];
    const float* b_out    = (const float*)d_in[7];
    float* out = (float*)d_out;

    int L = in_sizes[0] / 3;
    int tiles = (L + 63) / 64;

    const int prep_n = 2 * PLANE_U32;
    prep_weights<<<(prep_n + 255) / 256, 256>>>(W_first, W_hidden);

    cudaFuncSetAttribute(inr_mma_kernel,
                         cudaFuncAttributeMaxDynamicSharedMemorySize,
                         SMEM_BYTES);
    inr_mma_kernel<<<tiles, THREADS, SMEM_BYTES>>>(
        coords, B_ff, b_first, b_hidden, W_out, b_out, out, L);
}